// round 15
// baseline (speedup 1.0000x reference)
#include <cuda_runtime.h>
#include <cuda_bf16.h>
#include <cstdint>

#define Bn  16
#define Qn  64
#define Kn  1024
#define Dn  256
#define Hn  128
#define DVn 256

// Scratch (device globals; no allocation allowed in kernel_launch)
__device__ float g_kproj[Bn * Kn * Hn];   // 8 MB (rows >= ceil64(vlen) stay 0)
__device__ float g_qproj[Bn * Qn * Hn];   // 0.5 MB
__device__ float g_escores[Bn * Qn * Kn]; // 4 MB: exp(score), masked -> 0
__device__ float g_rowsum[Bn * Qn];       // per-row sum of exp (atomic)

__device__ __forceinline__ float fast_tanh(float x) {
    float y;
    asm("tanh.approx.f32 %0, %1;" : "=f"(y) : "f"(x));
    return y;
}

// ---------------------------------------------------------------------------
// mma.sync m16n8k16 bf16 (row.col) fp32 accum; ldmatrix fragment loaders.
// All compute_80+ PTX (the harness's compute_100 virtual target rejects
// tcgen05; these pass).
// ---------------------------------------------------------------------------
__device__ __forceinline__ void mma16816(float* d, const uint32_t* a,
                                         const uint32_t* b) {
    asm volatile(
        "mma.sync.aligned.m16n8k16.row.col.f32.bf16.bf16.f32 "
        "{%0,%1,%2,%3}, {%4,%5,%6,%7}, {%8,%9}, {%0,%1,%2,%3};"
        : "+f"(d[0]), "+f"(d[1]), "+f"(d[2]), "+f"(d[3])
        : "r"(a[0]), "r"(a[1]), "r"(a[2]), "r"(a[3]), "r"(b[0]), "r"(b[1]));
}

__device__ __forceinline__ void ldm_x4(uint32_t* r, const __nv_bfloat16* p) {
    uint32_t a = (uint32_t)__cvta_generic_to_shared(p);
    asm volatile(
        "ldmatrix.sync.aligned.m8n8.x4.shared.b16 {%0,%1,%2,%3}, [%4];"
        : "=r"(r[0]), "=r"(r[1]), "=r"(r[2]), "=r"(r[3]) : "r"(a));
}
__device__ __forceinline__ void ldm_x4t(uint32_t* r, const __nv_bfloat16* p) {
    uint32_t a = (uint32_t)__cvta_generic_to_shared(p);
    asm volatile(
        "ldmatrix.sync.aligned.m8n8.x4.trans.shared.b16 {%0,%1,%2,%3}, [%4];"
        : "=r"(r[0]), "=r"(r[1]), "=r"(r[2]), "=r"(r[3]) : "r"(a));
}

__device__ __forceinline__ __nv_bfloat162 hi2(float a, float b) {
    return __halves2bfloat162(__float2bfloat16(a), __float2bfloat16(b));
}
__device__ __forceinline__ __nv_bfloat162 lo2(float a, float b) {
    return __halves2bfloat162(
        __float2bfloat16(a - __bfloat162float(__float2bfloat16(a))),
        __float2bfloat16(b - __bfloat162float(__float2bfloat16(b))));
}

#define KC 32
#define APAD 40   // A tiles [m][32+8]: ldmatrix phases conflict-free
#define WPAD 136  // 128-col tiles [32][128+8]: row stride 68 words mod 32 = 4

// ---------------------------------------------------------------------------
// Projection via HMMA, split-bf16 3-product. R15: 64-row tiles (was 128) ->
// 272 CTAs, ~145 live after vlen skip, 2 CTAs/SM (regs<=128) -> the wave
// critical path halves (R14 skipped CTAs but wave time stayed at the
// full-size CTA duration). 8 warps 2(M) x 4(N); warp tile 32x32.
// ---------------------------------------------------------------------------
__global__ void __launch_bounds__(256, 2) proj_mma_kernel(
    const float* __restrict__ keys, const float* __restrict__ queries,
    const float* __restrict__ Wk, const float* __restrict__ Wq,
    const int* __restrict__ vlen) {
    __shared__ __align__(16) __nv_bfloat16 sAh[64][APAD];
    __shared__ __align__(16) __nv_bfloat16 sAl[64][APAD];
    __shared__ __align__(16) __nv_bfloat16 sWh[32][WPAD];  // [d][h] natural
    __shared__ __align__(16) __nv_bfloat16 sWl[32][WPAD];

    const int tid  = threadIdx.x;
    const int wid  = tid >> 5;
    const int lane = tid & 31;
    const int cid  = blockIdx.x;

    const float* X;
    const float* W;
    float* P;
    int row0;
    if (cid < 256) {
        // kproj: 16 CTAs per batch, 64 rows each; skip past masked boundary.
        const int b     = cid >> 4;
        const int local = (cid & 15) * 64;
        if (local >= ((vlen[b] + 63) & ~63)) return;
        X = keys; W = Wk; P = g_kproj; row0 = cid * 64;
    } else {
        X = queries; W = Wq; P = g_qproj; row0 = (cid - 256) * 64;
    }

    const int wm   = (wid & 1) * 32;
    const int wn   = (wid >> 1) * 32;
    const int gid  = lane >> 2;
    const int tig  = lane & 3;
    const int lrow = lane & 15;
    const int lcol = (lane >> 4) * 8;

    float acc[2][4][4];
#pragma unroll
    for (int im = 0; im < 2; im++)
#pragma unroll
        for (int j = 0; j < 4; j++)
#pragma unroll
            for (int r = 0; r < 4; r++) acc[im][j][r] = 0.f;

    float4 xPre[2], wPre[4];
#pragma unroll
    for (int i = 0; i < 2; i++) {
        int idx = tid + i * 256;
        int r = idx >> 3, kq = idx & 7;
        xPre[i] = *(const float4*)&X[(size_t)(row0 + r) * Dn + kq * 4];
    }
#pragma unroll
    for (int i = 0; i < 4; i++) {
        int idx = tid + i * 256;
        int k = idx >> 5, n4 = idx & 31;
        wPre[i] = *(const float4*)&W[(size_t)k * Hn + n4 * 4];
    }

    for (int kc = 0; kc < Dn; kc += KC) {
#pragma unroll
        for (int i = 0; i < 2; i++) {
            int idx = tid + i * 256;
            int r = idx >> 3, kq = idx & 7;
            float4 v = xPre[i];
            *(__nv_bfloat162*)&sAh[r][kq * 4]     = hi2(v.x, v.y);
            *(__nv_bfloat162*)&sAh[r][kq * 4 + 2] = hi2(v.z, v.w);
            *(__nv_bfloat162*)&sAl[r][kq * 4]     = lo2(v.x, v.y);
            *(__nv_bfloat162*)&sAl[r][kq * 4 + 2] = lo2(v.z, v.w);
        }
#pragma unroll
        for (int i = 0; i < 4; i++) {
            int idx = tid + i * 256;
            int k = idx >> 5, n4 = idx & 31;
            float4 v = wPre[i];
            *(__nv_bfloat162*)&sWh[k][n4 * 4]     = hi2(v.x, v.y);
            *(__nv_bfloat162*)&sWh[k][n4 * 4 + 2] = hi2(v.z, v.w);
            *(__nv_bfloat162*)&sWl[k][n4 * 4]     = lo2(v.x, v.y);
            *(__nv_bfloat162*)&sWl[k][n4 * 4 + 2] = lo2(v.z, v.w);
        }
        __syncthreads();

        if (kc + KC < Dn) {
#pragma unroll
            for (int i = 0; i < 2; i++) {
                int idx = tid + i * 256;
                int r = idx >> 3, kq = idx & 7;
                xPre[i] = *(const float4*)
                    &X[(size_t)(row0 + r) * Dn + kc + KC + kq * 4];
            }
#pragma unroll
            for (int i = 0; i < 4; i++) {
                int idx = tid + i * 256;
                int k = idx >> 5, n4 = idx & 31;
                wPre[i] = *(const float4*)
                    &W[(size_t)(kc + KC + k) * Hn + n4 * 4];
            }
        }

#pragma unroll
        for (int s = 0; s < 2; s++) {
            uint32_t Ah[2][4], Al[2][4];
#pragma unroll
            for (int im = 0; im < 2; im++) {
                ldm_x4(Ah[im], &sAh[wm + im * 16 + lrow][s * 16 + lcol]);
                ldm_x4(Al[im], &sAl[wm + im * 16 + lrow][s * 16 + lcol]);
            }
            uint32_t Bh[4][2], Bl[4][2];
#pragma unroll
            for (int jj = 0; jj < 2; jj++) {
                uint32_t t[4];
                ldm_x4t(t, &sWh[s * 16 + lrow][wn + jj * 16 + lcol]);
                Bh[jj * 2][0] = t[0]; Bh[jj * 2][1] = t[1];
                Bh[jj * 2 + 1][0] = t[2]; Bh[jj * 2 + 1][1] = t[3];
                ldm_x4t(t, &sWl[s * 16 + lrow][wn + jj * 16 + lcol]);
                Bl[jj * 2][0] = t[0]; Bl[jj * 2][1] = t[1];
                Bl[jj * 2 + 1][0] = t[2]; Bl[jj * 2 + 1][1] = t[3];
            }
#pragma unroll
            for (int im = 0; im < 2; im++) {
#pragma unroll
                for (int j = 0; j < 4; j++) {
                    mma16816(acc[im][j], Ah[im], Bh[j]);
                    mma16816(acc[im][j], Al[im], Bh[j]);
                    mma16816(acc[im][j], Ah[im], Bl[j]);
                }
            }
        }
        __syncthreads();
    }

#pragma unroll
    for (int im = 0; im < 2; im++) {
        int r_lo = row0 + wm + im * 16 + gid;
#pragma unroll
        for (int j = 0; j < 4; j++) {
            int c = wn + j * 8 + tig * 2;
            *(float2*)&P[(size_t)r_lo * Hn + c] =
                make_float2(acc[im][j][0], acc[im][j][1]);
            *(float2*)&P[(size_t)(r_lo + 8) * Hn + c] =
                make_float2(acc[im][j][2], acc[im][j][3]);
        }
    }
}

// ---------------------------------------------------------------------------
// scores: emits exp(score) (no max subtraction — |score| <~ 4) with
// k >= vlen masked to exactly 0; atomic per-row sums. Early-exit on dead
// 64-chunks; zero-fill dead 32-tiles inside live chunks.
// fp32 tanh.approx — at its MUFU floor; f16x2 lost twice (R9, R11).
// CTA = (k-tile 32, q-half 32, b).
// ---------------------------------------------------------------------------
__global__ void scores_kernel(const float* __restrict__ wv,
                              const int* __restrict__ vlen) {
    const int b   = blockIdx.z;
    const int qh  = blockIdx.y * 32;
    const int k0  = blockIdx.x * 32;
    const int tid = threadIdx.x;

    const int vl = vlen[b];
    if ((k0 & ~63) >= vl) return;  // whole 64-chunk dead: never read by av

    const int kk = tid & 31;
    const int q0 = (tid >> 5) * 4;
    float* srow = g_escores + ((size_t)b * Qn + qh) * Kn + k0 + kk;

    if (k0 >= vl) {
        // dead 32-tile inside a live 64-chunk: av reads it -> zero it
#pragma unroll
        for (int qi = 0; qi < 4; qi++) {
            srow[(size_t)(q0 + qi) * Kn] = 0.f;
        }
        return;
    }

    __shared__ __align__(16) float sQ[32][Hn];
    __shared__ __align__(16) float sK[32][132];
    __shared__ __align__(16) float sWv[Hn];

    {
        const float4* src =
            (const float4*)(g_qproj + ((size_t)b * Qn + qh) * Hn);
        float4* dst = (float4*)&sQ[0][0];
#pragma unroll
        for (int i = 0; i < 4; i++) {
            int j = tid + i * 256;
            dst[j] = src[j];
        }
    }
    {
        const float4* src =
            (const float4*)(g_kproj + ((size_t)b * Kn + k0) * Hn);
#pragma unroll
        for (int i = 0; i < 4; i++) {
            int j   = tid + i * 256;
            int row = j >> 5;
            int c4  = j & 31;
            *(float4*)&sK[row][c4 * 4] = src[j];
        }
    }
    if (tid < Hn) sWv[tid] = wv[tid];
    __syncthreads();

    float sc[4];
    sc[0] = sc[1] = sc[2] = sc[3] = 0.f;

#pragma unroll 4
    for (int h = 0; h < Hn; h += 4) {
        float4 kv = *(const float4*)&sK[kk][h];
        float4 w4 = *(const float4*)&sWv[h];
#pragma unroll
        for (int qi = 0; qi < 4; qi++) {
            float4 qv = *(const float4*)&sQ[q0 + qi][h];
            sc[qi] += w4.x * fast_tanh(qv.x + kv.x);
            sc[qi] += w4.y * fast_tanh(qv.y + kv.y);
            sc[qi] += w4.z * fast_tanh(qv.z + kv.z);
            sc[qi] += w4.w * fast_tanh(qv.w + kv.w);
        }
    }

    const bool valid = (k0 + kk) < vl;
#pragma unroll
    for (int qi = 0; qi < 4; qi++) {
        float e = valid ? __expf(sc[qi]) : 0.f;
        srow[(size_t)(q0 + qi) * Kn] = e;
        float t = e;
#pragma unroll
        for (int o = 16; o; o >>= 1) t += __shfl_xor_sync(0xffffffffu, t, o);
        if (kk == 0) atomicAdd(&g_rowsum[b * Qn + qh + q0 + qi], t);
    }
}

// ---------------------------------------------------------------------------
// Zero d_out (poisoned before timing; av accumulates atomically) and
// g_rowsum (accumulated atomically every call — graph replay safe).
// ---------------------------------------------------------------------------
__global__ void zero_out_kernel(float* __restrict__ out) {
    const int idx = blockIdx.x * 256 + threadIdx.x;  // 65536 float4
    ((float4*)out)[idx] = make_float4(0.f, 0.f, 0.f, 0.f);
    if (idx < Bn * Qn / 4) {
        ((float4*)g_rowsum)[idx] = make_float4(0.f, 0.f, 0.f, 0.f);
    }
}

// ---------------------------------------------------------------------------
// AV as HMMA GEMM with fused normalization: attn = escore * (1/rowsum).
// R15: n-split x2 -> grid (16 ck, 2 nh, Bn) = 512 CTAs (~270 live), each
// 64q x 128dv x 64k; warp tile 32x32, regs <= 128 -> 2 CTAs/SM -> one wave
// with cross-CTA latency hiding (R14: 1 CTA/SM, occ 11.9%). Only cost is
// re-staging the tiny 64x64 attn tile per n-half.
// Epilogue: atomicAdd into pre-zeroed out. 8 warps 2(M) x 4(N).
// ---------------------------------------------------------------------------
__global__ void __launch_bounds__(256, 2) av_mma_kernel(
    const float* __restrict__ V, const int* __restrict__ vlen,
    float* __restrict__ out) {
    const int b  = blockIdx.z;
    const int ck = blockIdx.x;
    const int n0 = blockIdx.y * 128;
    const int k0 = ck * 64;
    if (k0 >= vlen[b]) return;  // uniform per CTA

    __shared__ __align__(16) __nv_bfloat16 sAh[64][APAD];  // attn [q][k]
    __shared__ __align__(16) __nv_bfloat16 sAl[64][APAD];
    __shared__ __align__(16) __nv_bfloat16 sVh[32][WPAD];  // V [k][n] natural
    __shared__ __align__(16) __nv_bfloat16 sVl[32][WPAD];
    __shared__ float sIS[64];                              // per-q 1/rowsum

    const int tid  = threadIdx.x;
    const int wid  = tid >> 5;
    const int lane = tid & 31;
    const int gid  = lane >> 2;
    const int tig  = lane & 3;
    const int lrow = lane & 15;
    const int lcol = (lane >> 4) * 8;
    const int wm   = (wid & 1) * 32;   // 2 x 32 = 64 q
    const int wn   = (wid >> 1) * 32;  // 4 x 32 = 128 dv

    if (tid < 64) sIS[tid] = 1.0f / g_rowsum[b * Qn + tid];

    float acc[2][4][4];
#pragma unroll
    for (int im = 0; im < 2; im++)
#pragma unroll
        for (int j = 0; j < 4; j++)
#pragma unroll
            for (int r = 0; r < 4; r++) acc[im][j][r] = 0.f;

    const float* Ab = g_escores + ((size_t)b * Qn) * Kn + k0;
    const float* Vb = V + ((size_t)b * Kn + k0) * DVn + n0;

    float4 aPre[2], vPre[4];
#pragma unroll
    for (int i = 0; i < 2; i++) {
        int idx = tid + i * 256;
        int r = idx >> 3, kq = idx & 7;
        aPre[i] = *(const float4*)&Ab[(size_t)r * Kn + kq * 4];
    }
#pragma unroll
    for (int i = 0; i < 4; i++) {
        int idx = tid + i * 256;
        int k = idx >> 5, n4 = idx & 31;
        vPre[i] = *(const float4*)&Vb[(size_t)k * DVn + n4 * 4];
    }
    __syncthreads();  // sIS visible before first staging conversion

    for (int kc = 0; kc < 64; kc += KC) {
#pragma unroll
        for (int i = 0; i < 2; i++) {
            int idx = tid + i * 256;
            int r = idx >> 3, kq = idx & 7;
            float4 v = aPre[i];
            float is = sIS[r];
            float px = v.x * is, py = v.y * is;
            float pz = v.z * is, pw = v.w * is;
            *(__nv_bfloat162*)&sAh[r][kq * 4]     = hi2(px, py);
            *(__nv_bfloat162*)&sAh[r][kq * 4 + 2] = hi2(pz, pw);
            *(__nv_bfloat162*)&sAl[r][kq * 4]     = lo2(px, py);
            *(__nv_bfloat162*)&sAl[r][kq * 4 + 2] = lo2(pz, pw);
        }
#pragma unroll
        for (int i = 0; i < 4; i++) {
            int idx = tid + i * 256;
            int k = idx >> 5, n4 = idx & 31;
            float4 v = vPre[i];
            *(__nv_bfloat162*)&sVh[k][n4 * 4]     = hi2(v.x, v.y);
            *(__nv_bfloat162*)&sVh[k][n4 * 4 + 2] = hi2(v.z, v.w);
            *(__nv_bfloat162*)&sVl[k][n4 * 4]     = lo2(v.x, v.y);
            *(__nv_bfloat162*)&sVl[k][n4 * 4 + 2] = lo2(v.z, v.w);
        }
        __syncthreads();

        if (kc + KC < 64) {
#pragma unroll
            for (int i = 0; i < 2; i++) {
                int idx = tid + i * 256;
                int r = idx >> 3, kq = idx & 7;
                aPre[i] = *(const float4*)
                    &Ab[(size_t)r * Kn + kc + KC + kq * 4];
            }
#pragma unroll
            for (int i = 0; i < 4; i++) {
                int idx = tid + i * 256;
                int k = idx >> 5, n4 = idx & 31;
                vPre[i] = *(const float4*)
                    &Vb[(size_t)(kc + KC + k) * DVn + n4 * 4];
            }
        }

#pragma unroll
        for (int s = 0; s < 2; s++) {
            uint32_t Ah2[2][4], Al2[2][4];
#pragma unroll
            for (int im = 0; im < 2; im++) {
                ldm_x4(Ah2[im], &sAh[wm + im * 16 + lrow][s * 16 + lcol]);
                ldm_x4(Al2[im], &sAl[wm + im * 16 + lrow][s * 16 + lcol]);
            }
            uint32_t Bh[4][2], Bl[4][2];
#pragma unroll
            for (int jj = 0; jj < 2; jj++) {
                uint32_t t[4];
                ldm_x4t(t, &sVh[s * 16 + lrow][wn + jj * 16 + lcol]);
                Bh[jj * 2][0] = t[0]; Bh[jj * 2][1] = t[1];
                Bh[jj * 2 + 1][0] = t[2]; Bh[jj * 2 + 1][1] = t[3];
                ldm_x4t(t, &sVl[s * 16 + lrow][wn + jj * 16 + lcol]);
                Bl[jj * 2][0] = t[0]; Bl[jj * 2][1] = t[1];
                Bl[jj * 2 + 1][0] = t[2]; Bl[jj * 2 + 1][1] = t[3];
            }
#pragma unroll
            for (int im = 0; im < 2; im++) {
#pragma unroll
                for (int j = 0; j < 4; j++) {
                    mma16816(acc[im][j], Ah2[im], Bh[j]);
                    mma16816(acc[im][j], Al2[im], Bh[j]);
                    mma16816(acc[im][j], Ah2[im], Bl[j]);
                }
            }
        }
        __syncthreads();
    }

    float* Ob = out + ((size_t)b * Qn) * DVn + n0;
#pragma unroll
    for (int im = 0; im < 2; im++) {
        int r = wm + im * 16 + gid;
#pragma unroll
        for (int j = 0; j < 4; j++) {
            int c = wn + j * 8 + tig * 2;
            atomicAdd(&Ob[(size_t)r * DVn + c],           acc[im][j][0]);
            atomicAdd(&Ob[(size_t)r * DVn + c + 1],       acc[im][j][1]);
            atomicAdd(&Ob[(size_t)(r + 8) * DVn + c],     acc[im][j][2]);
            atomicAdd(&Ob[(size_t)(r + 8) * DVn + c + 1], acc[im][j][3]);
        }
    }
}

// ---------------------------------------------------------------------------
extern "C" void kernel_launch(void* const* d_in, const int* in_sizes, int n_in,
                              void* d_out, int out_size) {
    const float* queries = (const float*)d_in[0];
    const float* keys    = (const float*)d_in[1];
    const float* values  = (const float*)d_in[2];
    const int*   vlens   = (const int*)d_in[3];
    const float* Wq      = (const float*)d_in[4];
    const float* Wk      = (const float*)d_in[5];
    const float* wv      = (const float*)d_in[6];
    float* out           = (float*)d_out;

    zero_out_kernel<<<Bn * Qn * DVn / 1024, 256>>>(out);
    proj_mma_kernel<<<272, 256>>>(keys, queries, Wk, Wq, vlens);
    scores_kernel<<<dim3(Kn / 32, 2, Bn), 256>>>(wv, vlens);
    av_mma_kernel<<<dim3(16, 2, Bn), 256>>>(values, vlens, out);
}

// round 16
// speedup vs baseline: 1.0763x; 1.0763x over previous
#include <cuda_runtime.h>
#include <cuda_bf16.h>
#include <cstdint>

#define Bn  16
#define Qn  64
#define Kn  1024
#define Dn  256
#define Hn  128
#define DVn 256

// Scratch (device globals; no allocation allowed in kernel_launch)
__device__ float g_kproj[Bn * Kn * Hn];   // 8 MB (rows >= ceil64(vlen) stay 0)
__device__ float g_qproj[Bn * Qn * Hn];   // 0.5 MB
__device__ float g_escores[Bn * Qn * Kn]; // 4 MB: exp(score), masked -> 0
__device__ float g_rowsum[Bn * Qn];       // per-row sum of exp (atomic)

__device__ __forceinline__ float fast_tanh(float x) {
    float y;
    asm("tanh.approx.f32 %0, %1;" : "=f"(y) : "f"(x));
    return y;
}

// ---------------------------------------------------------------------------
// mma.sync m16n8k16 bf16 (row.col) fp32 accum; ldmatrix fragment loaders.
// All compute_80+ PTX (the harness's compute_100 virtual target rejects
// tcgen05; these pass).
// ---------------------------------------------------------------------------
__device__ __forceinline__ void mma16816(float* d, const uint32_t* a,
                                         const uint32_t* b) {
    asm volatile(
        "mma.sync.aligned.m16n8k16.row.col.f32.bf16.bf16.f32 "
        "{%0,%1,%2,%3}, {%4,%5,%6,%7}, {%8,%9}, {%0,%1,%2,%3};"
        : "+f"(d[0]), "+f"(d[1]), "+f"(d[2]), "+f"(d[3])
        : "r"(a[0]), "r"(a[1]), "r"(a[2]), "r"(a[3]), "r"(b[0]), "r"(b[1]));
}

__device__ __forceinline__ void ldm_x4(uint32_t* r, const __nv_bfloat16* p) {
    uint32_t a = (uint32_t)__cvta_generic_to_shared(p);
    asm volatile(
        "ldmatrix.sync.aligned.m8n8.x4.shared.b16 {%0,%1,%2,%3}, [%4];"
        : "=r"(r[0]), "=r"(r[1]), "=r"(r[2]), "=r"(r[3]) : "r"(a));
}
__device__ __forceinline__ void ldm_x4t(uint32_t* r, const __nv_bfloat16* p) {
    uint32_t a = (uint32_t)__cvta_generic_to_shared(p);
    asm volatile(
        "ldmatrix.sync.aligned.m8n8.x4.trans.shared.b16 {%0,%1,%2,%3}, [%4];"
        : "=r"(r[0]), "=r"(r[1]), "=r"(r[2]), "=r"(r[3]) : "r"(a));
}

__device__ __forceinline__ __nv_bfloat162 hi2(float a, float b) {
    return __halves2bfloat162(__float2bfloat16(a), __float2bfloat16(b));
}
__device__ __forceinline__ __nv_bfloat162 lo2(float a, float b) {
    return __halves2bfloat162(
        __float2bfloat16(a - __bfloat162float(__float2bfloat16(a))),
        __float2bfloat16(b - __bfloat162float(__float2bfloat16(b))));
}

#define KC 32
#define APAD 40   // A tiles [m][32+8]: ldmatrix phases conflict-free
#define WPAD 136  // 128-col tiles [32][128+8]: row stride 68 words mod 32 = 4

// ---------------------------------------------------------------------------
// Projection via HMMA, split-bf16 3-product. R16: 128-row tile (R15's 64-row
// tiles duplicated W staging -> regression) but with 512 THREADS (16 warps,
// 4Mx4N, warp tile 32x32): doubles staging parallelism and gives 4 warps per
// SMSP to overlap the stage->sync->MMA phases that serialize at 8 warps.
// Grid 136 CTAs (kproj vlen-skip) + prefetch + ldmatrix (R10 machinery).
// ---------------------------------------------------------------------------
__global__ void __launch_bounds__(512, 1) proj_mma_kernel(
    const float* __restrict__ keys, const float* __restrict__ queries,
    const float* __restrict__ Wk, const float* __restrict__ Wq,
    const int* __restrict__ vlen) {
    __shared__ __align__(16) __nv_bfloat16 sAh[128][APAD];
    __shared__ __align__(16) __nv_bfloat16 sAl[128][APAD];
    __shared__ __align__(16) __nv_bfloat16 sWh[32][WPAD];  // [d][h] natural
    __shared__ __align__(16) __nv_bfloat16 sWl[32][WPAD];

    const int tid  = threadIdx.x;
    const int wid  = tid >> 5;
    const int lane = tid & 31;
    const int cid  = blockIdx.x;

    const float* X;
    const float* W;
    float* P;
    int row0;
    if (cid < 128) {
        // kproj: 8 CTAs per batch, 128 rows; skip past masked boundary.
        const int b     = cid >> 3;
        const int local = (cid & 7) * 128;
        if (local >= ((vlen[b] + 63) & ~63)) return;
        X = keys; W = Wk; P = g_kproj; row0 = cid * 128;
    } else {
        X = queries; W = Wq; P = g_qproj; row0 = (cid - 128) * 128;
    }

    const int wm   = (wid & 3) * 32;   // 4 x 32 = 128 rows
    const int wn   = (wid >> 2) * 32;  // 4 x 32 = 128 cols
    const int gid  = lane >> 2;
    const int tig  = lane & 3;
    const int lrow = lane & 15;
    const int lcol = (lane >> 4) * 8;

    float acc[2][4][4];
#pragma unroll
    for (int im = 0; im < 2; im++)
#pragma unroll
        for (int j = 0; j < 4; j++)
#pragma unroll
            for (int r = 0; r < 4; r++) acc[im][j][r] = 0.f;

    float4 xPre[2], wPre[2];
#pragma unroll
    for (int i = 0; i < 2; i++) {
        int idx = tid + i * 512;           // 1024 float4 (128 x 32)
        int r = idx >> 3, kq = idx & 7;
        xPre[i] = *(const float4*)&X[(size_t)(row0 + r) * Dn + kq * 4];
    }
#pragma unroll
    for (int i = 0; i < 2; i++) {
        int idx = tid + i * 512;           // 1024 float4 (32 x 128)
        int k = idx >> 5, n4 = idx & 31;
        wPre[i] = *(const float4*)&W[(size_t)k * Hn + n4 * 4];
    }

    for (int kc = 0; kc < Dn; kc += KC) {
#pragma unroll
        for (int i = 0; i < 2; i++) {
            int idx = tid + i * 512;
            int r = idx >> 3, kq = idx & 7;
            float4 v = xPre[i];
            *(__nv_bfloat162*)&sAh[r][kq * 4]     = hi2(v.x, v.y);
            *(__nv_bfloat162*)&sAh[r][kq * 4 + 2] = hi2(v.z, v.w);
            *(__nv_bfloat162*)&sAl[r][kq * 4]     = lo2(v.x, v.y);
            *(__nv_bfloat162*)&sAl[r][kq * 4 + 2] = lo2(v.z, v.w);
        }
#pragma unroll
        for (int i = 0; i < 2; i++) {
            int idx = tid + i * 512;
            int k = idx >> 5, n4 = idx & 31;
            float4 v = wPre[i];
            *(__nv_bfloat162*)&sWh[k][n4 * 4]     = hi2(v.x, v.y);
            *(__nv_bfloat162*)&sWh[k][n4 * 4 + 2] = hi2(v.z, v.w);
            *(__nv_bfloat162*)&sWl[k][n4 * 4]     = lo2(v.x, v.y);
            *(__nv_bfloat162*)&sWl[k][n4 * 4 + 2] = lo2(v.z, v.w);
        }
        __syncthreads();

        if (kc + KC < Dn) {
#pragma unroll
            for (int i = 0; i < 2; i++) {
                int idx = tid + i * 512;
                int r = idx >> 3, kq = idx & 7;
                xPre[i] = *(const float4*)
                    &X[(size_t)(row0 + r) * Dn + kc + KC + kq * 4];
            }
#pragma unroll
            for (int i = 0; i < 2; i++) {
                int idx = tid + i * 512;
                int k = idx >> 5, n4 = idx & 31;
                wPre[i] = *(const float4*)
                    &W[(size_t)(kc + KC + k) * Hn + n4 * 4];
            }
        }

#pragma unroll
        for (int s = 0; s < 2; s++) {
            uint32_t Ah[2][4], Al[2][4];
#pragma unroll
            for (int im = 0; im < 2; im++) {
                ldm_x4(Ah[im], &sAh[wm + im * 16 + lrow][s * 16 + lcol]);
                ldm_x4(Al[im], &sAl[wm + im * 16 + lrow][s * 16 + lcol]);
            }
            uint32_t Bh[4][2], Bl[4][2];
#pragma unroll
            for (int jj = 0; jj < 2; jj++) {
                uint32_t t[4];
                ldm_x4t(t, &sWh[s * 16 + lrow][wn + jj * 16 + lcol]);
                Bh[jj * 2][0] = t[0]; Bh[jj * 2][1] = t[1];
                Bh[jj * 2 + 1][0] = t[2]; Bh[jj * 2 + 1][1] = t[3];
                ldm_x4t(t, &sWl[s * 16 + lrow][wn + jj * 16 + lcol]);
                Bl[jj * 2][0] = t[0]; Bl[jj * 2][1] = t[1];
                Bl[jj * 2 + 1][0] = t[2]; Bl[jj * 2 + 1][1] = t[3];
            }
#pragma unroll
            for (int im = 0; im < 2; im++) {
#pragma unroll
                for (int j = 0; j < 4; j++) {
                    mma16816(acc[im][j], Ah[im], Bh[j]);
                    mma16816(acc[im][j], Al[im], Bh[j]);
                    mma16816(acc[im][j], Ah[im], Bl[j]);
                }
            }
        }
        __syncthreads();
    }

#pragma unroll
    for (int im = 0; im < 2; im++) {
        int r_lo = row0 + wm + im * 16 + gid;
#pragma unroll
        for (int j = 0; j < 4; j++) {
            int c = wn + j * 8 + tig * 2;
            *(float2*)&P[(size_t)r_lo * Hn + c] =
                make_float2(acc[im][j][0], acc[im][j][1]);
            *(float2*)&P[(size_t)(r_lo + 8) * Hn + c] =
                make_float2(acc[im][j][2], acc[im][j][3]);
        }
    }
}

// ---------------------------------------------------------------------------
// scores: emits exp(score) (no max subtraction — |score| <~ 4) with
// k >= vlen masked to exactly 0; atomic per-row sums. Early-exit on dead
// 64-chunks; zero-fill dead 32-tiles inside live chunks.
// fp32 tanh.approx — at its MUFU floor; f16x2 lost twice (R9, R11).
// CTA = (k-tile 32, q-half 32, b).
// ---------------------------------------------------------------------------
__global__ void scores_kernel(const float* __restrict__ wv,
                              const int* __restrict__ vlen) {
    const int b   = blockIdx.z;
    const int qh  = blockIdx.y * 32;
    const int k0  = blockIdx.x * 32;
    const int tid = threadIdx.x;

    const int vl = vlen[b];
    if ((k0 & ~63) >= vl) return;  // whole 64-chunk dead: never read by av

    const int kk = tid & 31;
    const int q0 = (tid >> 5) * 4;
    float* srow = g_escores + ((size_t)b * Qn + qh) * Kn + k0 + kk;

    if (k0 >= vl) {
        // dead 32-tile inside a live 64-chunk: av reads it -> zero it
#pragma unroll
        for (int qi = 0; qi < 4; qi++) {
            srow[(size_t)(q0 + qi) * Kn] = 0.f;
        }
        return;
    }

    __shared__ __align__(16) float sQ[32][Hn];
    __shared__ __align__(16) float sK[32][132];
    __shared__ __align__(16) float sWv[Hn];

    {
        const float4* src =
            (const float4*)(g_qproj + ((size_t)b * Qn + qh) * Hn);
        float4* dst = (float4*)&sQ[0][0];
#pragma unroll
        for (int i = 0; i < 4; i++) {
            int j = tid + i * 256;
            dst[j] = src[j];
        }
    }
    {
        const float4* src =
            (const float4*)(g_kproj + ((size_t)b * Kn + k0) * Hn);
#pragma unroll
        for (int i = 0; i < 4; i++) {
            int j   = tid + i * 256;
            int row = j >> 5;
            int c4  = j & 31;
            *(float4*)&sK[row][c4 * 4] = src[j];
        }
    }
    if (tid < Hn) sWv[tid] = wv[tid];
    __syncthreads();

    float sc[4];
    sc[0] = sc[1] = sc[2] = sc[3] = 0.f;

#pragma unroll 4
    for (int h = 0; h < Hn; h += 4) {
        float4 kv = *(const float4*)&sK[kk][h];
        float4 w4 = *(const float4*)&sWv[h];
#pragma unroll
        for (int qi = 0; qi < 4; qi++) {
            float4 qv = *(const float4*)&sQ[q0 + qi][h];
            sc[qi] += w4.x * fast_tanh(qv.x + kv.x);
            sc[qi] += w4.y * fast_tanh(qv.y + kv.y);
            sc[qi] += w4.z * fast_tanh(qv.z + kv.z);
            sc[qi] += w4.w * fast_tanh(qv.w + kv.w);
        }
    }

    const bool valid = (k0 + kk) < vl;
#pragma unroll
    for (int qi = 0; qi < 4; qi++) {
        float e = valid ? __expf(sc[qi]) : 0.f;
        srow[(size_t)(q0 + qi) * Kn] = e;
        float t = e;
#pragma unroll
        for (int o = 16; o; o >>= 1) t += __shfl_xor_sync(0xffffffffu, t, o);
        if (kk == 0) atomicAdd(&g_rowsum[b * Qn + qh + q0 + qi], t);
    }
}

// ---------------------------------------------------------------------------
// Zero d_out (poisoned before timing; av accumulates atomically) and
// g_rowsum (accumulated atomically every call — graph replay safe).
// ---------------------------------------------------------------------------
__global__ void zero_out_kernel(float* __restrict__ out) {
    const int idx = blockIdx.x * 256 + threadIdx.x;  // 65536 float4
    ((float4*)out)[idx] = make_float4(0.f, 0.f, 0.f, 0.f);
    if (idx < Bn * Qn / 4) {
        ((float4*)g_rowsum)[idx] = make_float4(0.f, 0.f, 0.f, 0.f);
    }
}

// ---------------------------------------------------------------------------
// AV as HMMA GEMM with fused normalization: attn = escore * (1/rowsum).
// R15 version (measured win 11.4 -> 10.4): grid (16 ck, 2 nh, Bn) = 512
// CTAs, each 64q x 128dv x 64k; 2 CTAs/SM. atomicAdd epilogue.
// 8 warps 2(M) x 4(N); warp tile 32x32.
// ---------------------------------------------------------------------------
__global__ void __launch_bounds__(256, 2) av_mma_kernel(
    const float* __restrict__ V, const int* __restrict__ vlen,
    float* __restrict__ out) {
    const int b  = blockIdx.z;
    const int ck = blockIdx.x;
    const int n0 = blockIdx.y * 128;
    const int k0 = ck * 64;
    if (k0 >= vlen[b]) return;  // uniform per CTA

    __shared__ __align__(16) __nv_bfloat16 sAh[64][APAD];  // attn [q][k]
    __shared__ __align__(16) __nv_bfloat16 sAl[64][APAD];
    __shared__ __align__(16) __nv_bfloat16 sVh[32][WPAD];  // V [k][n] natural
    __shared__ __align__(16) __nv_bfloat16 sVl[32][WPAD];
    __shared__ float sIS[64];                              // per-q 1/rowsum

    const int tid  = threadIdx.x;
    const int wid  = tid >> 5;
    const int lane = tid & 31;
    const int gid  = lane >> 2;
    const int tig  = lane & 3;
    const int lrow = lane & 15;
    const int lcol = (lane >> 4) * 8;
    const int wm   = (wid & 1) * 32;   // 2 x 32 = 64 q
    const int wn   = (wid >> 1) * 32;  // 4 x 32 = 128 dv

    if (tid < 64) sIS[tid] = 1.0f / g_rowsum[b * Qn + tid];

    float acc[2][4][4];
#pragma unroll
    for (int im = 0; im < 2; im++)
#pragma unroll
        for (int j = 0; j < 4; j++)
#pragma unroll
            for (int r = 0; r < 4; r++) acc[im][j][r] = 0.f;

    const float* Ab = g_escores + ((size_t)b * Qn) * Kn + k0;
    const float* Vb = V + ((size_t)b * Kn + k0) * DVn + n0;

    float4 aPre[2], vPre[4];
#pragma unroll
    for (int i = 0; i < 2; i++) {
        int idx = tid + i * 256;
        int r = idx >> 3, kq = idx & 7;
        aPre[i] = *(const float4*)&Ab[(size_t)r * Kn + kq * 4];
    }
#pragma unroll
    for (int i = 0; i < 4; i++) {
        int idx = tid + i * 256;
        int k = idx >> 5, n4 = idx & 31;
        vPre[i] = *(const float4*)&Vb[(size_t)k * DVn + n4 * 4];
    }
    __syncthreads();  // sIS visible before first staging conversion

    for (int kc = 0; kc < 64; kc += KC) {
#pragma unroll
        for (int i = 0; i < 2; i++) {
            int idx = tid + i * 256;
            int r = idx >> 3, kq = idx & 7;
            float4 v = aPre[i];
            float is = sIS[r];
            float px = v.x * is, py = v.y * is;
            float pz = v.z * is, pw = v.w * is;
            *(__nv_bfloat162*)&sAh[r][kq * 4]     = hi2(px, py);
            *(__nv_bfloat162*)&sAh[r][kq * 4 + 2] = hi2(pz, pw);
            *(__nv_bfloat162*)&sAl[r][kq * 4]     = lo2(px, py);
            *(__nv_bfloat162*)&sAl[r][kq * 4 + 2] = lo2(pz, pw);
        }
#pragma unroll
        for (int i = 0; i < 4; i++) {
            int idx = tid + i * 256;
            int k = idx >> 5, n4 = idx & 31;
            float4 v = vPre[i];
            *(__nv_bfloat162*)&sVh[k][n4 * 4]     = hi2(v.x, v.y);
            *(__nv_bfloat162*)&sVh[k][n4 * 4 + 2] = hi2(v.z, v.w);
            *(__nv_bfloat162*)&sVl[k][n4 * 4]     = lo2(v.x, v.y);
            *(__nv_bfloat162*)&sVl[k][n4 * 4 + 2] = lo2(v.z, v.w);
        }
        __syncthreads();

        if (kc + KC < 64) {
#pragma unroll
            for (int i = 0; i < 2; i++) {
                int idx = tid + i * 256;
                int r = idx >> 3, kq = idx & 7;
                aPre[i] = *(const float4*)
                    &Ab[(size_t)r * Kn + kc + KC + kq * 4];
            }
#pragma unroll
            for (int i = 0; i < 4; i++) {
                int idx = tid + i * 256;
                int k = idx >> 5, n4 = idx & 31;
                vPre[i] = *(const float4*)
                    &Vb[(size_t)(kc + KC + k) * DVn + n4 * 4];
            }
        }

#pragma unroll
        for (int s = 0; s < 2; s++) {
            uint32_t Ah2[2][4], Al2[2][4];
#pragma unroll
            for (int im = 0; im < 2; im++) {
                ldm_x4(Ah2[im], &sAh[wm + im * 16 + lrow][s * 16 + lcol]);
                ldm_x4(Al2[im], &sAl[wm + im * 16 + lrow][s * 16 + lcol]);
            }
            uint32_t Bh[4][2], Bl[4][2];
#pragma unroll
            for (int jj = 0; jj < 2; jj++) {
                uint32_t t[4];
                ldm_x4t(t, &sVh[s * 16 + lrow][wn + jj * 16 + lcol]);
                Bh[jj * 2][0] = t[0]; Bh[jj * 2][1] = t[1];
                Bh[jj * 2 + 1][0] = t[2]; Bh[jj * 2 + 1][1] = t[3];
                ldm_x4t(t, &sVl[s * 16 + lrow][wn + jj * 16 + lcol]);
                Bl[jj * 2][0] = t[0]; Bl[jj * 2][1] = t[1];
                Bl[jj * 2 + 1][0] = t[2]; Bl[jj * 2 + 1][1] = t[3];
            }
#pragma unroll
            for (int im = 0; im < 2; im++) {
#pragma unroll
                for (int j = 0; j < 4; j++) {
                    mma16816(acc[im][j], Ah2[im], Bh[j]);
                    mma16816(acc[im][j], Al2[im], Bh[j]);
                    mma16816(acc[im][j], Ah2[im], Bl[j]);
                }
            }
        }
        __syncthreads();
    }

    float* Ob = out + ((size_t)b * Qn) * DVn + n0;
#pragma unroll
    for (int im = 0; im < 2; im++) {
        int r = wm + im * 16 + gid;
#pragma unroll
        for (int j = 0; j < 4; j++) {
            int c = wn + j * 8 + tig * 2;
            atomicAdd(&Ob[(size_t)r * DVn + c],           acc[im][j][0]);
            atomicAdd(&Ob[(size_t)r * DVn + c + 1],       acc[im][j][1]);
            atomicAdd(&Ob[(size_t)(r + 8) * DVn + c],     acc[im][j][2]);
            atomicAdd(&Ob[(size_t)(r + 8) * DVn + c + 1], acc[im][j][3]);
        }
    }
}

// ---------------------------------------------------------------------------
extern "C" void kernel_launch(void* const* d_in, const int* in_sizes, int n_in,
                              void* d_out, int out_size) {
    const float* queries = (const float*)d_in[0];
    const float* keys    = (const float*)d_in[1];
    const float* values  = (const float*)d_in[2];
    const int*   vlens   = (const int*)d_in[3];
    const float* Wq      = (const float*)d_in[4];
    const float* Wk      = (const float*)d_in[5];
    const float* wv      = (const float*)d_in[6];
    float* out           = (float*)d_out;

    zero_out_kernel<<<Bn * Qn * DVn / 1024, 256>>>(out);
    proj_mma_kernel<<<136, 512>>>(keys, queries, Wk, Wq, vlens);
    scores_kernel<<<dim3(Kn / 32, 2, Bn), 256>>>(wv, vlens);
    av_mma_kernel<<<dim3(16, 2, Bn), 256>>>(values, vlens, out);
}

// round 17
// speedup vs baseline: 1.1158x; 1.0367x over previous
#include <cuda_runtime.h>
#include <cuda_bf16.h>
#include <cstdint>

#define Bn  16
#define Qn  64
#define Kn  1024
#define Dn  256
#define Hn  128
#define DVn 256

// Scratch (device globals; no allocation allowed in kernel_launch)
__device__ float g_kproj[Bn * Kn * Hn];   // 8 MB (rows >= ceil64(vlen) stay 0)
__device__ float g_qproj[Bn * Qn * Hn];   // 0.5 MB
__device__ float g_escores[Bn * Qn * Kn]; // 4 MB: exp(score), masked -> 0
__device__ float g_rowsum[Bn * Qn];       // per-row sum of exp (atomic)

__device__ __forceinline__ float fast_tanh(float x) {
    float y;
    asm("tanh.approx.f32 %0, %1;" : "=f"(y) : "f"(x));
    return y;
}

// ---------------------------------------------------------------------------
// mma.sync m16n8k16 bf16 (row.col) fp32 accum; ldmatrix fragment loaders.
// All compute_80+ PTX (the harness's compute_100 virtual target rejects
// tcgen05; these pass).
// ---------------------------------------------------------------------------
__device__ __forceinline__ void mma16816(float* d, const uint32_t* a,
                                         const uint32_t* b) {
    asm volatile(
        "mma.sync.aligned.m16n8k16.row.col.f32.bf16.bf16.f32 "
        "{%0,%1,%2,%3}, {%4,%5,%6,%7}, {%8,%9}, {%0,%1,%2,%3};"
        : "+f"(d[0]), "+f"(d[1]), "+f"(d[2]), "+f"(d[3])
        : "r"(a[0]), "r"(a[1]), "r"(a[2]), "r"(a[3]), "r"(b[0]), "r"(b[1]));
}

__device__ __forceinline__ void ldm_x4(uint32_t* r, const __nv_bfloat16* p) {
    uint32_t a = (uint32_t)__cvta_generic_to_shared(p);
    asm volatile(
        "ldmatrix.sync.aligned.m8n8.x4.shared.b16 {%0,%1,%2,%3}, [%4];"
        : "=r"(r[0]), "=r"(r[1]), "=r"(r[2]), "=r"(r[3]) : "r"(a));
}
__device__ __forceinline__ void ldm_x4t(uint32_t* r, const __nv_bfloat16* p) {
    uint32_t a = (uint32_t)__cvta_generic_to_shared(p);
    asm volatile(
        "ldmatrix.sync.aligned.m8n8.x4.trans.shared.b16 {%0,%1,%2,%3}, [%4];"
        : "=r"(r[0]), "=r"(r[1]), "=r"(r[2]), "=r"(r[3]) : "r"(a));
}

__device__ __forceinline__ __nv_bfloat162 hi2(float a, float b) {
    return __halves2bfloat162(__float2bfloat16(a), __float2bfloat16(b));
}
__device__ __forceinline__ __nv_bfloat162 lo2(float a, float b) {
    return __halves2bfloat162(
        __float2bfloat16(a - __bfloat162float(__float2bfloat16(a))),
        __float2bfloat16(b - __bfloat162float(__float2bfloat16(b))));
}

#define KC 32
#define APAD 40   // A tiles [m][32+8]: ldmatrix phases conflict-free
#define WPAD 136  // 128-col tiles [32][128+8]: row stride 68 words mod 32 = 4

// Per-stage dynamic-smem layouts (bytes)
#define P_AH 0
#define P_AL (128 * APAD * 2)
#define P_WH (2 * 128 * APAD * 2)
#define P_WL (2 * 128 * APAD * 2 + 32 * WPAD * 2)
#define P_STAGE (2 * 128 * APAD * 2 + 2 * 32 * WPAD * 2)  // 37888

#define A_AH 0
#define A_AL (64 * APAD * 2)
#define A_VH (2 * 64 * APAD * 2)
#define A_VL (2 * 64 * APAD * 2 + 32 * WPAD * 2)
#define A_STAGE (2 * 64 * APAD * 2 + 2 * 32 * WPAD * 2)   // 27648

// ---------------------------------------------------------------------------
// Projection via HMMA, split-bf16 3-product. R17: 2-stage smem ping-pong —
// one sync per chunk; convert of chunk+1 (into the other stage) overlaps the
// MMA phase (R16 serialized stage->sync->MMA->sync, ~2x the MMA floor).
// 512 threads, 16 warps 4Mx4N, 128x128 tile, kproj vlen-skip, dynamic smem.
// ---------------------------------------------------------------------------
__global__ void __launch_bounds__(512, 1) proj_mma_kernel(
    const float* __restrict__ keys, const float* __restrict__ queries,
    const float* __restrict__ Wk, const float* __restrict__ Wq,
    const int* __restrict__ vlen) {
    extern __shared__ __align__(16) char dsm[];

    const int tid  = threadIdx.x;
    const int wid  = tid >> 5;
    const int lane = tid & 31;
    const int cid  = blockIdx.x;

    const float* X;
    const float* W;
    float* P;
    int row0;
    if (cid < 128) {
        const int b     = cid >> 3;
        const int local = (cid & 7) * 128;
        if (local >= ((vlen[b] + 63) & ~63)) return;
        X = keys; W = Wk; P = g_kproj; row0 = cid * 128;
    } else {
        X = queries; W = Wq; P = g_qproj; row0 = (cid - 128) * 128;
    }

    const int wm   = (wid & 3) * 32;
    const int wn   = (wid >> 2) * 32;
    const int gid  = lane >> 2;
    const int tig  = lane & 3;
    const int lrow = lane & 15;
    const int lcol = (lane >> 4) * 8;

    float acc[2][4][4];
#pragma unroll
    for (int im = 0; im < 2; im++)
#pragma unroll
        for (int j = 0; j < 4; j++)
#pragma unroll
            for (int r = 0; r < 4; r++) acc[im][j][r] = 0.f;

    // staging index precompute
    const int ar0 = tid >> 3, akq0 = (tid & 7) * 4;           // i=0
    const int ar1 = (tid + 512) >> 3, akq1 = (tid & 7) * 4;   // i=1 (same kq)
    const int wk0 = tid >> 5, wn0 = (tid & 31) * 4;
    const int wk1 = (tid + 512) >> 5, wn1 = (tid & 31) * 4;

    float4 xPre[2], wPre[2];
    xPre[0] = *(const float4*)&X[(size_t)(row0 + ar0) * Dn + akq0];
    xPre[1] = *(const float4*)&X[(size_t)(row0 + ar1) * Dn + akq1];
    wPre[0] = *(const float4*)&W[(size_t)wk0 * Hn + wn0];
    wPre[1] = *(const float4*)&W[(size_t)wk1 * Hn + wn1];

    // convert chunk 0 into stage 0
    {
        char* st = dsm;
#pragma unroll
        for (int i = 0; i < 2; i++) {
            int r = i ? ar1 : ar0, kq = i ? akq1 : akq0;
            float4 v = xPre[i];
            __nv_bfloat16* ah = (__nv_bfloat16*)(st + P_AH) + r * APAD + kq;
            __nv_bfloat16* al = (__nv_bfloat16*)(st + P_AL) + r * APAD + kq;
            *(__nv_bfloat162*)(ah)     = hi2(v.x, v.y);
            *(__nv_bfloat162*)(ah + 2) = hi2(v.z, v.w);
            *(__nv_bfloat162*)(al)     = lo2(v.x, v.y);
            *(__nv_bfloat162*)(al + 2) = lo2(v.z, v.w);
        }
#pragma unroll
        for (int i = 0; i < 2; i++) {
            int k = i ? wk1 : wk0, n4 = i ? wn1 : wn0;
            float4 v = wPre[i];
            __nv_bfloat16* wh = (__nv_bfloat16*)(st + P_WH) + k * WPAD + n4;
            __nv_bfloat16* wl = (__nv_bfloat16*)(st + P_WL) + k * WPAD + n4;
            *(__nv_bfloat162*)(wh)     = hi2(v.x, v.y);
            *(__nv_bfloat162*)(wh + 2) = hi2(v.z, v.w);
            *(__nv_bfloat162*)(wl)     = lo2(v.x, v.y);
            *(__nv_bfloat162*)(wl + 2) = lo2(v.z, v.w);
        }
    }

    const int NCH = Dn / KC;  // 8
    for (int ch = 0; ch < NCH; ch++) {
        __syncthreads();

        // prefetch regs for ch+1 (global latency hidden under MMA)
        if (ch + 1 < NCH) {
            const int kc = (ch + 1) * KC;
            xPre[0] = *(const float4*)&X[(size_t)(row0 + ar0) * Dn + kc + akq0];
            xPre[1] = *(const float4*)&X[(size_t)(row0 + ar1) * Dn + kc + akq1];
            wPre[0] = *(const float4*)&W[(size_t)(kc + wk0) * Hn + wn0];
            wPre[1] = *(const float4*)&W[(size_t)(kc + wk1) * Hn + wn1];
        }

        // ---- MMA from stage ch&1 ----
        char* cur = dsm + (ch & 1) * P_STAGE;
        const __nv_bfloat16* cAh = (const __nv_bfloat16*)(cur + P_AH);
        const __nv_bfloat16* cAl = (const __nv_bfloat16*)(cur + P_AL);
        const __nv_bfloat16* cWh = (const __nv_bfloat16*)(cur + P_WH);
        const __nv_bfloat16* cWl = (const __nv_bfloat16*)(cur + P_WL);
#pragma unroll
        for (int s = 0; s < 2; s++) {
            uint32_t Ah[2][4], Al[2][4];
#pragma unroll
            for (int im = 0; im < 2; im++) {
                ldm_x4(Ah[im],
                       cAh + (wm + im * 16 + lrow) * APAD + s * 16 + lcol);
                ldm_x4(Al[im],
                       cAl + (wm + im * 16 + lrow) * APAD + s * 16 + lcol);
            }
            uint32_t Bh[4][2], Bl[4][2];
#pragma unroll
            for (int jj = 0; jj < 2; jj++) {
                uint32_t t[4];
                ldm_x4t(t, cWh + (s * 16 + lrow) * WPAD + wn + jj * 16 + lcol);
                Bh[jj * 2][0] = t[0]; Bh[jj * 2][1] = t[1];
                Bh[jj * 2 + 1][0] = t[2]; Bh[jj * 2 + 1][1] = t[3];
                ldm_x4t(t, cWl + (s * 16 + lrow) * WPAD + wn + jj * 16 + lcol);
                Bl[jj * 2][0] = t[0]; Bl[jj * 2][1] = t[1];
                Bl[jj * 2 + 1][0] = t[2]; Bl[jj * 2 + 1][1] = t[3];
            }
#pragma unroll
            for (int im = 0; im < 2; im++) {
#pragma unroll
                for (int j = 0; j < 4; j++) {
                    mma16816(acc[im][j], Ah[im], Bh[j]);
                    mma16816(acc[im][j], Al[im], Bh[j]);
                    mma16816(acc[im][j], Ah[im], Bl[j]);
                }
            }
        }

        // ---- convert ch+1 into the other stage (overlaps peers' MMA) ----
        if (ch + 1 < NCH) {
            char* nxt = dsm + ((ch + 1) & 1) * P_STAGE;
#pragma unroll
            for (int i = 0; i < 2; i++) {
                int r = i ? ar1 : ar0, kq = i ? akq1 : akq0;
                float4 v = xPre[i];
                __nv_bfloat16* ah = (__nv_bfloat16*)(nxt + P_AH) + r * APAD + kq;
                __nv_bfloat16* al = (__nv_bfloat16*)(nxt + P_AL) + r * APAD + kq;
                *(__nv_bfloat162*)(ah)     = hi2(v.x, v.y);
                *(__nv_bfloat162*)(ah + 2) = hi2(v.z, v.w);
                *(__nv_bfloat162*)(al)     = lo2(v.x, v.y);
                *(__nv_bfloat162*)(al + 2) = lo2(v.z, v.w);
            }
#pragma unroll
            for (int i = 0; i < 2; i++) {
                int k = i ? wk1 : wk0, n4 = i ? wn1 : wn0;
                float4 v = wPre[i];
                __nv_bfloat16* wh = (__nv_bfloat16*)(nxt + P_WH) + k * WPAD + n4;
                __nv_bfloat16* wl = (__nv_bfloat16*)(nxt + P_WL) + k * WPAD + n4;
                *(__nv_bfloat162*)(wh)     = hi2(v.x, v.y);
                *(__nv_bfloat162*)(wh + 2) = hi2(v.z, v.w);
                *(__nv_bfloat162*)(wl)     = lo2(v.x, v.y);
                *(__nv_bfloat162*)(wl + 2) = lo2(v.z, v.w);
            }
        }
    }

#pragma unroll
    for (int im = 0; im < 2; im++) {
        int r_lo = row0 + wm + im * 16 + gid;
#pragma unroll
        for (int j = 0; j < 4; j++) {
            int c = wn + j * 8 + tig * 2;
            *(float2*)&P[(size_t)r_lo * Hn + c] =
                make_float2(acc[im][j][0], acc[im][j][1]);
            *(float2*)&P[(size_t)(r_lo + 8) * Hn + c] =
                make_float2(acc[im][j][2], acc[im][j][3]);
        }
    }
}

// ---------------------------------------------------------------------------
// scores: emits exp(score) (no max subtraction — |score| <~ 4) with
// k >= vlen masked to exactly 0; atomic per-row sums. Early-exit on dead
// 64-chunks; zero-fill dead 32-tiles inside live chunks.
// fp32 tanh.approx — at its MUFU floor; f16x2 lost twice (R9, R11).
// CTA = (k-tile 32, q-half 32, b).
// ---------------------------------------------------------------------------
__global__ void scores_kernel(const float* __restrict__ wv,
                              const int* __restrict__ vlen) {
    const int b   = blockIdx.z;
    const int qh  = blockIdx.y * 32;
    const int k0  = blockIdx.x * 32;
    const int tid = threadIdx.x;

    const int vl = vlen[b];
    if ((k0 & ~63) >= vl) return;  // whole 64-chunk dead: never read by av

    const int kk = tid & 31;
    const int q0 = (tid >> 5) * 4;
    float* srow = g_escores + ((size_t)b * Qn + qh) * Kn + k0 + kk;

    if (k0 >= vl) {
#pragma unroll
        for (int qi = 0; qi < 4; qi++) {
            srow[(size_t)(q0 + qi) * Kn] = 0.f;
        }
        return;
    }

    __shared__ __align__(16) float sQ[32][Hn];
    __shared__ __align__(16) float sK[32][132];
    __shared__ __align__(16) float sWv[Hn];

    {
        const float4* src =
            (const float4*)(g_qproj + ((size_t)b * Qn + qh) * Hn);
        float4* dst = (float4*)&sQ[0][0];
#pragma unroll
        for (int i = 0; i < 4; i++) {
            int j = tid + i * 256;
            dst[j] = src[j];
        }
    }
    {
        const float4* src =
            (const float4*)(g_kproj + ((size_t)b * Kn + k0) * Hn);
#pragma unroll
        for (int i = 0; i < 4; i++) {
            int j   = tid + i * 256;
            int row = j >> 5;
            int c4  = j & 31;
            *(float4*)&sK[row][c4 * 4] = src[j];
        }
    }
    if (tid < Hn) sWv[tid] = wv[tid];
    __syncthreads();

    float sc[4];
    sc[0] = sc[1] = sc[2] = sc[3] = 0.f;

#pragma unroll 4
    for (int h = 0; h < Hn; h += 4) {
        float4 kv = *(const float4*)&sK[kk][h];
        float4 w4 = *(const float4*)&sWv[h];
#pragma unroll
        for (int qi = 0; qi < 4; qi++) {
            float4 qv = *(const float4*)&sQ[q0 + qi][h];
            sc[qi] += w4.x * fast_tanh(qv.x + kv.x);
            sc[qi] += w4.y * fast_tanh(qv.y + kv.y);
            sc[qi] += w4.z * fast_tanh(qv.z + kv.z);
            sc[qi] += w4.w * fast_tanh(qv.w + kv.w);
        }
    }

    const bool valid = (k0 + kk) < vl;
#pragma unroll
    for (int qi = 0; qi < 4; qi++) {
        float e = valid ? __expf(sc[qi]) : 0.f;
        srow[(size_t)(q0 + qi) * Kn] = e;
        float t = e;
#pragma unroll
        for (int o = 16; o; o >>= 1) t += __shfl_xor_sync(0xffffffffu, t, o);
        if (kk == 0) atomicAdd(&g_rowsum[b * Qn + qh + q0 + qi], t);
    }
}

// ---------------------------------------------------------------------------
// Zero d_out (poisoned before timing; av accumulates atomically) and
// g_rowsum (accumulated atomically every call — graph replay safe).
// ---------------------------------------------------------------------------
__global__ void zero_out_kernel(float* __restrict__ out) {
    const int idx = blockIdx.x * 256 + threadIdx.x;  // 65536 float4
    ((float4*)out)[idx] = make_float4(0.f, 0.f, 0.f, 0.f);
    if (idx < Bn * Qn / 4) {
        ((float4*)g_rowsum)[idx] = make_float4(0.f, 0.f, 0.f, 0.f);
    }
}

// ---------------------------------------------------------------------------
// AV as HMMA GEMM, fused normalization (attn = escore * invS in staging).
// R17: 2-stage ping-pong like proj (dynamic smem, 2 CTAs/SM).
// Grid (16 ck, 2 nh, Bn) = 512 CTAs; 8 warps 2(M) x 4(N); warp tile 32x32.
// ---------------------------------------------------------------------------
__global__ void __launch_bounds__(256, 2) av_mma_kernel(
    const float* __restrict__ V, const int* __restrict__ vlen,
    float* __restrict__ out) {
    extern __shared__ __align__(16) char dsm[];
    __shared__ float sIS[64];

    const int b  = blockIdx.z;
    const int ck = blockIdx.x;
    const int n0 = blockIdx.y * 128;
    const int k0 = ck * 64;
    if (k0 >= vlen[b]) return;  // uniform per CTA

    const int tid  = threadIdx.x;
    const int wid  = tid >> 5;
    const int lane = tid & 31;
    const int gid  = lane >> 2;
    const int tig  = lane & 3;
    const int lrow = lane & 15;
    const int lcol = (lane >> 4) * 8;
    const int wm   = (wid & 1) * 32;
    const int wn   = (wid >> 1) * 32;

    if (tid < 64) sIS[tid] = 1.0f / g_rowsum[b * Qn + tid];

    float acc[2][4][4];
#pragma unroll
    for (int im = 0; im < 2; im++)
#pragma unroll
        for (int j = 0; j < 4; j++)
#pragma unroll
            for (int r = 0; r < 4; r++) acc[im][j][r] = 0.f;

    const float* Ab = g_escores + ((size_t)b * Qn) * Kn + k0;
    const float* Vb = V + ((size_t)b * Kn + k0) * DVn + n0;

    const int ar0 = tid >> 3, akq0 = (tid & 7) * 4;
    const int ar1 = (tid + 256) >> 3;
    const int vk0 = tid >> 5, vn0 = (tid & 31) * 4;
    const int vk1 = (tid + 256) >> 5, vk2 = (tid + 512) >> 5,
              vk3 = (tid + 768) >> 5;

    float4 aPre[2], vPre[4];
    aPre[0] = *(const float4*)&Ab[(size_t)ar0 * Kn + akq0];
    aPre[1] = *(const float4*)&Ab[(size_t)ar1 * Kn + akq0];
    vPre[0] = *(const float4*)&Vb[(size_t)vk0 * DVn + vn0];
    vPre[1] = *(const float4*)&Vb[(size_t)vk1 * DVn + vn0];
    vPre[2] = *(const float4*)&Vb[(size_t)vk2 * DVn + vn0];
    vPre[3] = *(const float4*)&Vb[(size_t)vk3 * DVn + vn0];
    __syncthreads();  // sIS visible

    // convert chunk 0 into stage 0
    {
        char* st = dsm;
#pragma unroll
        for (int i = 0; i < 2; i++) {
            int r = i ? ar1 : ar0;
            float4 v = aPre[i];
            float is = sIS[r];
            float px = v.x * is, py = v.y * is;
            float pz = v.z * is, pw = v.w * is;
            __nv_bfloat16* ah = (__nv_bfloat16*)(st + A_AH) + r * APAD + akq0;
            __nv_bfloat16* al = (__nv_bfloat16*)(st + A_AL) + r * APAD + akq0;
            *(__nv_bfloat162*)(ah)     = hi2(px, py);
            *(__nv_bfloat162*)(ah + 2) = hi2(pz, pw);
            *(__nv_bfloat162*)(al)     = lo2(px, py);
            *(__nv_bfloat162*)(al + 2) = lo2(pz, pw);
        }
#pragma unroll
        for (int i = 0; i < 4; i++) {
            int k = (i == 0) ? vk0 : (i == 1) ? vk1 : (i == 2) ? vk2 : vk3;
            float4 v = vPre[i];
            __nv_bfloat16* vh = (__nv_bfloat16*)(st + A_VH) + k * WPAD + vn0;
            __nv_bfloat16* vl = (__nv_bfloat16*)(st + A_VL) + k * WPAD + vn0;
            *(__nv_bfloat162*)(vh)     = hi2(v.x, v.y);
            *(__nv_bfloat162*)(vh + 2) = hi2(v.z, v.w);
            *(__nv_bfloat162*)(vl)     = lo2(v.x, v.y);
            *(__nv_bfloat162*)(vl + 2) = lo2(v.z, v.w);
        }
    }

    for (int ch = 0; ch < 2; ch++) {
        __syncthreads();

        if (ch == 0) {  // prefetch chunk 1
            aPre[0] = *(const float4*)&Ab[(size_t)ar0 * Kn + KC + akq0];
            aPre[1] = *(const float4*)&Ab[(size_t)ar1 * Kn + KC + akq0];
            vPre[0] = *(const float4*)&Vb[(size_t)(KC + vk0) * DVn + vn0];
            vPre[1] = *(const float4*)&Vb[(size_t)(KC + vk1) * DVn + vn0];
            vPre[2] = *(const float4*)&Vb[(size_t)(KC + vk2) * DVn + vn0];
            vPre[3] = *(const float4*)&Vb[(size_t)(KC + vk3) * DVn + vn0];
        }

        char* cur = dsm + (ch & 1) * A_STAGE;
        const __nv_bfloat16* cAh = (const __nv_bfloat16*)(cur + A_AH);
        const __nv_bfloat16* cAl = (const __nv_bfloat16*)(cur + A_AL);
        const __nv_bfloat16* cVh = (const __nv_bfloat16*)(cur + A_VH);
        const __nv_bfloat16* cVl = (const __nv_bfloat16*)(cur + A_VL);
#pragma unroll
        for (int s = 0; s < 2; s++) {
            uint32_t Ah2[2][4], Al2[2][4];
#pragma unroll
            for (int im = 0; im < 2; im++) {
                ldm_x4(Ah2[im],
                       cAh + (wm + im * 16 + lrow) * APAD + s * 16 + lcol);
                ldm_x4(Al2[im],
                       cAl + (wm + im * 16 + lrow) * APAD + s * 16 + lcol);
            }
            uint32_t Bh[4][2], Bl[4][2];
#pragma unroll
            for (int jj = 0; jj < 2; jj++) {
                uint32_t t[4];
                ldm_x4t(t, cVh + (s * 16 + lrow) * WPAD + wn + jj * 16 + lcol);
                Bh[jj * 2][0] = t[0]; Bh[jj * 2][1] = t[1];
                Bh[jj * 2 + 1][0] = t[2]; Bh[jj * 2 + 1][1] = t[3];
                ldm_x4t(t, cVl + (s * 16 + lrow) * WPAD + wn + jj * 16 + lcol);
                Bl[jj * 2][0] = t[0]; Bl[jj * 2][1] = t[1];
                Bl[jj * 2 + 1][0] = t[2]; Bl[jj * 2 + 1][1] = t[3];
            }
#pragma unroll
            for (int im = 0; im < 2; im++) {
#pragma unroll
                for (int j = 0; j < 4; j++) {
                    mma16816(acc[im][j], Ah2[im], Bh[j]);
                    mma16816(acc[im][j], Al2[im], Bh[j]);
                    mma16816(acc[im][j], Ah2[im], Bl[j]);
                }
            }
        }

        if (ch == 0) {  // convert chunk 1 into stage 1
            char* nxt = dsm + A_STAGE;
#pragma unroll
            for (int i = 0; i < 2; i++) {
                int r = i ? ar1 : ar0;
                float4 v = aPre[i];
                float is = sIS[r];
                float px = v.x * is, py = v.y * is;
                float pz = v.z * is, pw = v.w * is;
                __nv_bfloat16* ah =
                    (__nv_bfloat16*)(nxt + A_AH) + r * APAD + akq0;
                __nv_bfloat16* al =
                    (__nv_bfloat16*)(nxt + A_AL) + r * APAD + akq0;
                *(__nv_bfloat162*)(ah)     = hi2(px, py);
                *(__nv_bfloat162*)(ah + 2) = hi2(pz, pw);
                *(__nv_bfloat162*)(al)     = lo2(px, py);
                *(__nv_bfloat162*)(al + 2) = lo2(pz, pw);
            }
#pragma unroll
            for (int i = 0; i < 4; i++) {
                int k = (i == 0) ? vk0 : (i == 1) ? vk1 : (i == 2) ? vk2 : vk3;
                float4 v = vPre[i];
                __nv_bfloat16* vh =
                    (__nv_bfloat16*)(nxt + A_VH) + k * WPAD + vn0;
                __nv_bfloat16* vl =
                    (__nv_bfloat16*)(nxt + A_VL) + k * WPAD + vn0;
                *(__nv_bfloat162*)(vh)     = hi2(v.x, v.y);
                *(__nv_bfloat162*)(vh + 2) = hi2(v.z, v.w);
                *(__nv_bfloat162*)(vl)     = lo2(v.x, v.y);
                *(__nv_bfloat162*)(vl + 2) = lo2(v.z, v.w);
            }
        }
    }

    float* Ob = out + ((size_t)b * Qn) * DVn + n0;
#pragma unroll
    for (int im = 0; im < 2; im++) {
        int r = wm + im * 16 + gid;
#pragma unroll
        for (int j = 0; j < 4; j++) {
            int c = wn + j * 8 + tig * 2;
            atomicAdd(&Ob[(size_t)r * DVn + c],           acc[im][j][0]);
            atomicAdd(&Ob[(size_t)r * DVn + c + 1],       acc[im][j][1]);
            atomicAdd(&Ob[(size_t)(r + 8) * DVn + c],     acc[im][j][2]);
            atomicAdd(&Ob[(size_t)(r + 8) * DVn + c + 1], acc[im][j][3]);
        }
    }
}

// ---------------------------------------------------------------------------
extern "C" void kernel_launch(void* const* d_in, const int* in_sizes, int n_in,
                              void* d_out, int out_size) {
    const float* queries = (const float*)d_in[0];
    const float* keys    = (const float*)d_in[1];
    const float* values  = (const float*)d_in[2];
    const int*   vlens   = (const int*)d_in[3];
    const float* Wq      = (const float*)d_in[4];
    const float* Wk      = (const float*)d_in[5];
    const float* wv      = (const float*)d_in[6];
    float* out           = (float*)d_out;

    // Immediate driver calls (not stream ops) — safe under graph capture;
    // idempotent across replays.
    cudaFuncSetAttribute(proj_mma_kernel,
                         cudaFuncAttributeMaxDynamicSharedMemorySize,
                         2 * P_STAGE);
    cudaFuncSetAttribute(av_mma_kernel,
                         cudaFuncAttributeMaxDynamicSharedMemorySize,
                         2 * A_STAGE);

    zero_out_kernel<<<Bn * Qn * DVn / 1024, 256>>>(out);
    proj_mma_kernel<<<136, 512, 2 * P_STAGE>>>(keys, queries, Wk, Wq, vlens);
    scores_kernel<<<dim3(Kn / 32, 2, Bn), 256>>>(wv, vlens);
    av_mma_kernel<<<dim3(16, 2, Bn), 256, 2 * A_STAGE>>>(values, vlens, out);
}